// round 9
// baseline (speedup 1.0000x reference)
#include <cuda_runtime.h>
#include <cooperative_groups.h>
#include <math.h>

namespace cg = cooperative_groups;

#define BN 32768
#define DN 1024
#define CN 256
#define NB4 1024
#define MAXM 640          // max members/class (mean 128, sd ~11.3; 640 unreachable)
#define NCHUNK 128        // 32768 / 256

// Scratch — overwritten every launch where read (graph/replay safe).
__device__ __align__(16) float g_invnorm[BN];
__device__ __align__(16) int   g_order[CN * MAXM];
__device__ __align__(16) int   g_counts[CN];
__device__ __align__(16) int   g_hist[NCHUNK * CN];
__device__ __align__(16) int   g_cbase[NCHUNK * CN];
__device__ __align__(16) float g_partial[NB4];
__device__ int g_sem;     // 0 at start; last k_main block resets to 0 -> replay safe

// ---------------- R1: per-chunk class histogram (int atomics -> deterministic) -------
__global__ void k_hist(const int* __restrict__ labels) {
    __shared__ int h[CN];
    int tid = threadIdx.x;
    h[tid] = 0;
    __syncthreads();
    int lab = labels[blockIdx.x * 256 + tid];
    atomicAdd(&h[lab], 1);
    __syncthreads();
    g_hist[blockIdx.x * CN + tid] = h[tid];
}

// ---------------- R2: per-class exclusive prefix over chunks + totals ----------------
__global__ void k_scan() {
    int c = threadIdx.x;       // one thread per class
    int run = 0;
    for (int b = 0; b < NCHUNK; b += 8) {
        int vals[8];
        #pragma unroll
        for (int k = 0; k < 8; k++) vals[k] = g_hist[(b + k) * CN + c];
        #pragma unroll
        for (int k = 0; k < 8; k++) { g_cbase[(b + k) * CN + c] = run; run += vals[k]; }
    }
    g_counts[c] = run;
}

// ---------------- R3: within-chunk stable rank -> scatter member indices -------------
__global__ void k_rank(const int* __restrict__ labels) {
    __shared__ int labs[256];
    int tid = threadIdx.x;
    int j = blockIdx.x * 256 + tid;
    int lab = labels[j];
    labs[tid] = lab;
    __syncthreads();
    int rank = 0;
    for (int t = 0; t < tid; t++) rank += (labs[t] == lab);
    int pos = g_cbase[blockIdx.x * CN + lab] + rank;
    if (pos < MAXM) g_order[lab * MAXM + pos] = j;
}

// ---------------- K_main: fused sums (phase A) + loss (phase B), cluster of 4 --------
// grid = CN*4, cluster 4 = the 4 splits of one class. Phase A computes norms + split
// class-sum into smem; DSMEM exchange builds full class sum per block; phase B streams
// the same member rows again (L2-resident) computing LOO-centroid distances.
__global__ void __launch_bounds__(256) __cluster_dims__(4, 1, 1)
k_main(const float* __restrict__ feat, float* __restrict__ out) {
    int c = blockIdx.x >> 2;
    cg::cluster_group cluster = cg::this_cluster();
    int s = (int)cluster.block_rank();     // == blockIdx.x & 3
    int tid = threadIdx.x, lane = tid & 31, wid = tid >> 5;

    __shared__ float4 st4[8 * (DN / 4)];   // 32KB warp-combine staging
    __shared__ float4 sv_s[DN / 4];        // 4KB split class-sum (DSMEM-visible)

    int n = g_counts[c];
    int n_eff = (n < MAXM) ? n : MAXM;
    const int* __restrict__ ord = g_order + c * MAXM;
    const float4* __restrict__ f4 = (const float4*)feat;

    // ================= Phase A: norms + split class sum =================
    float4 acc[8];
    #pragma unroll
    for (int k = 0; k < 8; k++) acc[k] = make_float4(0.f, 0.f, 0.f, 0.f);

    int gw = s * 8 + wid;           // 0..31
    int r = gw;
    for (; r + 32 < n_eff; r += 64) {
        int m0 = ord[r], m1 = ord[r + 32];
        const float4* row0 = f4 + (size_t)m0 * (DN / 4);
        const float4* row1 = f4 + (size_t)m1 * (DN / 4);
        float4 v0[8], v1[8];
        #pragma unroll
        for (int k = 0; k < 8; k++) v0[k] = row0[k * 32 + lane];
        #pragma unroll
        for (int k = 0; k < 8; k++) v1[k] = row1[k * 32 + lane];
        float s0 = 0.f, s1 = 0.f;
        #pragma unroll
        for (int k = 0; k < 8; k++) {
            s0 += v0[k].x*v0[k].x + v0[k].y*v0[k].y + v0[k].z*v0[k].z + v0[k].w*v0[k].w;
            s1 += v1[k].x*v1[k].x + v1[k].y*v1[k].y + v1[k].z*v1[k].z + v1[k].w*v1[k].w;
        }
        #pragma unroll
        for (int o = 16; o; o >>= 1) {
            s0 += __shfl_xor_sync(0xffffffffu, s0, o);
            s1 += __shfl_xor_sync(0xffffffffu, s1, o);
        }
        float i0 = rsqrtf(fmaxf(s0, 1e-24f));
        float i1 = rsqrtf(fmaxf(s1, 1e-24f));
        if (lane == 0) { g_invnorm[m0] = i0; g_invnorm[m1] = i1; }
        #pragma unroll
        for (int k = 0; k < 8; k++) {
            acc[k].x += v0[k].x*i0 + v1[k].x*i1;
            acc[k].y += v0[k].y*i0 + v1[k].y*i1;
            acc[k].z += v0[k].z*i0 + v1[k].z*i1;
            acc[k].w += v0[k].w*i0 + v1[k].w*i1;
        }
    }
    for (; r < n_eff; r += 32) {
        int m0 = ord[r];
        const float4* row0 = f4 + (size_t)m0 * (DN / 4);
        float4 v0[8];
        #pragma unroll
        for (int k = 0; k < 8; k++) v0[k] = row0[k * 32 + lane];
        float s0 = 0.f;
        #pragma unroll
        for (int k = 0; k < 8; k++)
            s0 += v0[k].x*v0[k].x + v0[k].y*v0[k].y + v0[k].z*v0[k].z + v0[k].w*v0[k].w;
        #pragma unroll
        for (int o = 16; o; o >>= 1) s0 += __shfl_xor_sync(0xffffffffu, s0, o);
        float i0 = rsqrtf(fmaxf(s0, 1e-24f));
        if (lane == 0) g_invnorm[m0] = i0;
        #pragma unroll
        for (int k = 0; k < 8; k++) {
            acc[k].x += v0[k].x*i0; acc[k].y += v0[k].y*i0;
            acc[k].z += v0[k].z*i0; acc[k].w += v0[k].w*i0;
        }
    }

    // warp combine -> split sum in sv_s
    #pragma unroll
    for (int k = 0; k < 8; k++) st4[wid * (DN / 4) + k * 32 + lane] = acc[k];
    __syncthreads();
    {
        float4 t = st4[tid];
        #pragma unroll
        for (int w = 1; w < 8; w++) {
            float4 u = st4[w * (DN / 4) + tid];
            t.x += u.x; t.y += u.y; t.z += u.z; t.w += u.w;
        }
        sv_s[tid] = t;
    }
    __threadfence();          // order g_invnorm stores before peers read them
    cluster.sync();           // all 4 split sums + all invnorms ready

    // ============ DSMEM exchange: full class sum (fixed rank order) ============
    float4 sv = make_float4(0.f, 0.f, 0.f, 0.f);
    #pragma unroll
    for (int rr = 0; rr < 4; rr++) {
        const float4* p = (const float4*)cluster.map_shared_rank((void*)sv_s, rr);
        float4 u = p[tid];
        sv.x += u.x; sv.y += u.y; sv.z += u.z; sv.w += u.w;
    }
    cluster.sync();           // peers done reading sv_s before anyone may exit

    // ================= Phase B: LOO-centroid distances (L2 hits) =================
    float part = 0.f;
    if (n > 1) {
        float invden_ex = 1.0f / (float)(n - 1);
        float invden_no = 1.0f / (float)n;

        int rr = s;
        for (; rr + 4 < n_eff; rr += 8) {
            int i0 = ord[rr], i1 = ord[rr + 4];
            float in0 = g_invnorm[i0], in1 = g_invnorm[i1];
            float4 fv0 = f4[(size_t)i0 * (DN/4) + tid];
            float4 fv1 = f4[(size_t)i1 * (DN/4) + tid];
            {
                bool excl = (i0 < n);
                float invden = excl ? invden_ex : invden_no;
                float ex = 0.f, ey = 0.f, ez = 0.f, ew = 0.f;
                if (excl) {
                    int k = ord[i0];
                    float ik = g_invnorm[k];
                    float4 kv = f4[(size_t)k * (DN/4) + tid];
                    ex = kv.x*ik; ey = kv.y*ik; ez = kv.z*ik; ew = kv.w*ik;
                }
                float dx = fv0.x*in0 - (sv.x - ex)*invden;
                float dy = fv0.y*in0 - (sv.y - ey)*invden;
                float dz = fv0.z*in0 - (sv.z - ez)*invden;
                float dw = fv0.w*in0 - (sv.w - ew)*invden;
                part += dx*dx + dy*dy + dz*dz + dw*dw;
            }
            {
                bool excl = (i1 < n);
                float invden = excl ? invden_ex : invden_no;
                float ex = 0.f, ey = 0.f, ez = 0.f, ew = 0.f;
                if (excl) {
                    int k = ord[i1];
                    float ik = g_invnorm[k];
                    float4 kv = f4[(size_t)k * (DN/4) + tid];
                    ex = kv.x*ik; ey = kv.y*ik; ez = kv.z*ik; ew = kv.w*ik;
                }
                float dx = fv1.x*in1 - (sv.x - ex)*invden;
                float dy = fv1.y*in1 - (sv.y - ey)*invden;
                float dz = fv1.z*in1 - (sv.z - ez)*invden;
                float dw = fv1.w*in1 - (sv.w - ew)*invden;
                part += dx*dx + dy*dy + dz*dz + dw*dw;
            }
        }
        for (; rr < n_eff; rr += 4) {
            int i0 = ord[rr];
            float in0 = g_invnorm[i0];
            float4 fv0 = f4[(size_t)i0 * (DN/4) + tid];
            bool excl = (i0 < n);
            float invden = excl ? invden_ex : invden_no;
            float ex = 0.f, ey = 0.f, ez = 0.f, ew = 0.f;
            if (excl) {
                int k = ord[i0];
                float ik = g_invnorm[k];
                float4 kv = f4[(size_t)k * (DN/4) + tid];
                ex = kv.x*ik; ey = kv.y*ik; ez = kv.z*ik; ew = kv.w*ik;
            }
            float dx = fv0.x*in0 - (sv.x - ex)*invden;
            float dy = fv0.y*in0 - (sv.y - ey)*invden;
            float dz = fv0.z*in0 - (sv.z - ez)*invden;
            float dw = fv0.w*in0 - (sv.w - ew)*invden;
            part += dx*dx + dy*dy + dz*dz + dw*dw;
        }
    }

    // ============ block partial + fused deterministic final reduction ============
    #pragma unroll
    for (int o = 16; o; o >>= 1) part += __shfl_xor_sync(0xffffffffu, part, o);
    __shared__ float ws[8];
    __shared__ int amLast;
    if (lane == 0) ws[wid] = part;
    __syncthreads();
    if (tid == 0) {
        float t = 0.f;
        #pragma unroll
        for (int w = 0; w < 8; w++) t += ws[w];
        g_partial[blockIdx.x] = t;
        __threadfence();
        amLast = (atomicAdd(&g_sem, 1) == NB4 - 1);
    }
    __syncthreads();
    if (amLast) {
        float v = g_partial[tid] + g_partial[tid + 256]
                + g_partial[tid + 512] + g_partial[tid + 768];
        #pragma unroll
        for (int o = 16; o; o >>= 1) v += __shfl_xor_sync(0xffffffffu, v, o);
        if (lane == 0) ws[wid] = v;
        __syncthreads();
        if (tid == 0) {
            float t = 0.f;
            #pragma unroll
            for (int w = 0; w < 8; w++) t += ws[w];
            out[0] = 0.0005f * t / ((float)BN * (float)DN);
            g_sem = 0;   // reset for next replay
        }
    }
}

extern "C" void kernel_launch(void* const* d_in, const int* in_sizes, int n_in,
                              void* d_out, int out_size) {
    const float* feat  = (const float*)d_in[0];
    const int*  labels = (const int*)d_in[1];
    float* out = (float*)d_out;
    (void)in_sizes; (void)n_in; (void)out_size;

    k_hist<<<NCHUNK, 256>>>(labels);
    k_scan<<<1, 256>>>();
    k_rank<<<NCHUNK, 256>>>(labels);
    k_main<<<CN * 4, 256>>>(feat, out);
}

// round 12
// speedup vs baseline: 1.7305x; 1.7305x over previous
#include <cuda_runtime.h>
#include <math.h>

#define BN 32768
#define DN 1024
#define CN 256
#define MAXM 640          // max members/class (mean 128, sd ~11.3; 640 unreachable)
#define NCHUNK 128        // 32768 / 256

// Scratch — overwritten every launch where read (graph/replay safe).
__device__ __align__(16) float g_invnorm[BN];
__device__ __align__(16) int   g_order[CN * MAXM];
__device__ __align__(16) int   g_counts[CN];
__device__ __align__(16) int   g_hist[NCHUNK * CN];
__device__ __align__(16) int   g_cbase[NCHUNK * CN];
__device__ __align__(16) float g_sumsP[4][CN * DN];
__device__ __align__(16) float g_partial[CN];
__device__ int g_sem;     // 0 at start; last k_final2 block resets to 0 -> replay safe

// ---------------- R1: per-chunk class histogram (int atomics -> deterministic) -------
__global__ void k_hist(const int* __restrict__ labels) {
    __shared__ int h[CN];
    int tid = threadIdx.x;
    h[tid] = 0;
    __syncthreads();
    int lab = labels[blockIdx.x * 256 + tid];
    atomicAdd(&h[lab], 1);
    __syncthreads();
    g_hist[blockIdx.x * CN + tid] = h[tid];
}

// ---------------- R2: per-class exclusive prefix over chunks + totals ----------------
__global__ void k_scan() {
    int c = threadIdx.x;       // one thread per class
    int run = 0;
    for (int b = 0; b < NCHUNK; b += 8) {
        int vals[8];
        #pragma unroll
        for (int k = 0; k < 8; k++) vals[k] = g_hist[(b + k) * CN + c];
        #pragma unroll
        for (int k = 0; k < 8; k++) { g_cbase[(b + k) * CN + c] = run; run += vals[k]; }
    }
    g_counts[c] = run;
}

// ---------------- R3: within-chunk stable rank -> scatter member indices -------------
__global__ void k_rank(const int* __restrict__ labels) {
    __shared__ int labs[256];
    int tid = threadIdx.x;
    int j = blockIdx.x * 256 + tid;
    int lab = labels[j];
    labs[tid] = lab;
    __syncthreads();
    int rank = 0;
    for (int t = 0; t < tid; t++) rank += (labs[t] == lab);
    int pos = g_cbase[blockIdx.x * CN + lab] + rank;
    if (pos < MAXM) g_order[lab * MAXM + pos] = j;
}

// ---------------- K_sums: norms + class sums, 4 splits/class -------------------------
__global__ void __launch_bounds__(256) k_sums(const float* __restrict__ feat) {
    int c = blockIdx.x >> 2;
    int s = blockIdx.x & 3;
    int tid = threadIdx.x, lane = tid & 31, wid = tid >> 5;
    __shared__ float4 st4[8 * (DN / 4)];

    int n = g_counts[c];
    int n_eff = (n < MAXM) ? n : MAXM;
    const int* __restrict__ ord = g_order + c * MAXM;
    const float4* __restrict__ f4 = (const float4*)feat;

    float4 acc[8];
    #pragma unroll
    for (int k = 0; k < 8; k++) acc[k] = make_float4(0.f, 0.f, 0.f, 0.f);

    int gw = s * 8 + wid;           // 0..31
    int r = gw;
    for (; r + 32 < n_eff; r += 64) {
        int m0 = ord[r], m1 = ord[r + 32];
        const float4* row0 = f4 + (size_t)m0 * (DN / 4);
        const float4* row1 = f4 + (size_t)m1 * (DN / 4);
        float4 v0[8], v1[8];
        #pragma unroll
        for (int k = 0; k < 8; k++) v0[k] = row0[k * 32 + lane];
        #pragma unroll
        for (int k = 0; k < 8; k++) v1[k] = row1[k * 32 + lane];
        float s0 = 0.f, s1 = 0.f;
        #pragma unroll
        for (int k = 0; k < 8; k++) {
            s0 += v0[k].x*v0[k].x + v0[k].y*v0[k].y + v0[k].z*v0[k].z + v0[k].w*v0[k].w;
            s1 += v1[k].x*v1[k].x + v1[k].y*v1[k].y + v1[k].z*v1[k].z + v1[k].w*v1[k].w;
        }
        #pragma unroll
        for (int o = 16; o; o >>= 1) {
            s0 += __shfl_xor_sync(0xffffffffu, s0, o);
            s1 += __shfl_xor_sync(0xffffffffu, s1, o);
        }
        float i0 = rsqrtf(fmaxf(s0, 1e-24f));
        float i1 = rsqrtf(fmaxf(s1, 1e-24f));
        if (lane == 0) { g_invnorm[m0] = i0; g_invnorm[m1] = i1; }
        #pragma unroll
        for (int k = 0; k < 8; k++) {
            acc[k].x += v0[k].x*i0 + v1[k].x*i1;
            acc[k].y += v0[k].y*i0 + v1[k].y*i1;
            acc[k].z += v0[k].z*i0 + v1[k].z*i1;
            acc[k].w += v0[k].w*i0 + v1[k].w*i1;
        }
    }
    for (; r < n_eff; r += 32) {
        int m0 = ord[r];
        const float4* row0 = f4 + (size_t)m0 * (DN / 4);
        float4 v0[8];
        #pragma unroll
        for (int k = 0; k < 8; k++) v0[k] = row0[k * 32 + lane];
        float s0 = 0.f;
        #pragma unroll
        for (int k = 0; k < 8; k++)
            s0 += v0[k].x*v0[k].x + v0[k].y*v0[k].y + v0[k].z*v0[k].z + v0[k].w*v0[k].w;
        #pragma unroll
        for (int o = 16; o; o >>= 1) s0 += __shfl_xor_sync(0xffffffffu, s0, o);
        float i0 = rsqrtf(fmaxf(s0, 1e-24f));
        if (lane == 0) g_invnorm[m0] = i0;
        #pragma unroll
        for (int k = 0; k < 8; k++) {
            acc[k].x += v0[k].x*i0; acc[k].y += v0[k].y*i0;
            acc[k].z += v0[k].z*i0; acc[k].w += v0[k].w*i0;
        }
    }

    #pragma unroll
    for (int k = 0; k < 8; k++) st4[wid * (DN / 4) + k * 32 + lane] = acc[k];
    __syncthreads();
    float4 t = st4[tid];
    #pragma unroll
    for (int w = 1; w < 8; w++) {
        float4 u = st4[w * (DN / 4) + tid];
        t.x += u.x; t.y += u.y; t.z += u.z; t.w += u.w;
    }
    ((float4*)g_sumsP[s])[c * (DN / 4) + tid] = t;
}

// Block reduce helper: sums 'v' over 256 threads; result valid on tid 0.
__device__ __forceinline__ float blk_sum(float v, float* ws, int lane, int wid) {
    #pragma unroll
    for (int o = 16; o; o >>= 1) v += __shfl_xor_sync(0xffffffffu, v, o);
    if (lane == 0) ws[wid] = v;
    __syncthreads();
    float t = 0.f;
    if (wid == 0) {
        t = (lane < 8) ? ws[lane] : 0.f;
        #pragma unroll
        for (int o = 4; o; o >>= 1) t += __shfl_xor_sync(0xffffffffu, t, o);
    }
    __syncthreads();
    return t;  // valid on tid 0 (lane 0, wid 0)
}

// ---------------- K_final2: closed-form class loss + rare exclusion corrections ------
// Per class (one block): S = Σ splits; Q = ||S||²; raw = n − Q/n  (since ||f_i||²=1,
// Σ_i ||f_i − S/n||² = n − Q/n). Excluded samples (global i < n, ≈0.5/class) get the
// exact correction via 3 dot products. Deterministic fixed-order everywhere.
__global__ void __launch_bounds__(256) k_final2(const float* __restrict__ feat,
                                                float* __restrict__ out) {
    int c = blockIdx.x;
    int tid = threadIdx.x, lane = tid & 31, wid = tid >> 5;
    const float4* __restrict__ f4 = (const float4*)feat;
    __shared__ float ws[8];
    __shared__ float bc[3];
    __shared__ int amLast;

    // Combine 4 split partials -> S (one float4 per thread)
    float4 sv;
    {
        float4 a = ((const float4*)g_sumsP[0])[c * (DN/4) + tid];
        float4 b = ((const float4*)g_sumsP[1])[c * (DN/4) + tid];
        float4 d = ((const float4*)g_sumsP[2])[c * (DN/4) + tid];
        float4 e = ((const float4*)g_sumsP[3])[c * (DN/4) + tid];
        sv.x = a.x + b.x + d.x + e.x;
        sv.y = a.y + b.y + d.y + e.y;
        sv.z = a.z + b.z + d.z + e.z;
        sv.w = a.w + b.w + d.w + e.w;
    }

    int n = g_counts[c];
    float q = sv.x*sv.x + sv.y*sv.y + sv.z*sv.z + sv.w*sv.w;
    float Q = blk_sum(q, ws, lane, wid);      // valid on tid 0
    if (tid == 0) bc[0] = Q;                  // broadcast Q
    __syncthreads();
    Q = bc[0];

    float raw = 0.f;                          // accumulated on tid 0 only
    if (n > 1) {
        float fn = (float)n;
        if (tid == 0) raw = fn - Q / fn;

        // corrections: members whose global index < n (ord ascending -> early break)
        const int* __restrict__ ord = g_order + c * MAXM;
        int n_eff = (n < MAXM) ? n : MAXM;
        float nm1 = fn - 1.0f;
        for (int r = 0; r < n_eff; r++) {
            int i = ord[r];
            if (i >= n) break;                // uniform across block
            int k2 = ord[i];                  // excluded member (i < n <= MAXM)
            float inv_i = g_invnorm[i], inv_k = g_invnorm[k2];
            float4 va = f4[(size_t)i  * (DN/4) + tid];
            float4 vk = f4[(size_t)k2 * (DN/4) + tid];
            float pa = va.x*sv.x + va.y*sv.y + va.z*sv.z + va.w*sv.w;
            float pb = va.x*vk.x + va.y*vk.y + va.z*vk.z + va.w*vk.w;
            float pd = sv.x*vk.x + sv.y*vk.y + sv.z*vk.z + sv.w*vk.w;
            float A = blk_sum(pa, ws, lane, wid);
            float B = blk_sum(pb, ws, lane, wid);
            float D = blk_sum(pd, ws, lane, wid);
            if (tid == 0) {
                float a = A * inv_i;                 // f_i · S
                float b = B * inv_i * inv_k;         // f_i · f_k
                float d = D * inv_k;                 // S   · f_k
                float excl = -2.0f * (a - b) / nm1 + (Q - 2.0f * d + 1.0f) / (nm1 * nm1);
                float plain = -2.0f * a / fn + Q / (fn * fn);
                raw += excl - plain;
            }
        }
    }

    if (tid == 0) {
        g_partial[c] = raw;
        __threadfence();
        amLast = (atomicAdd(&g_sem, 1) == CN - 1);
    }
    __syncthreads();
    if (amLast) {
        float v = g_partial[tid];
        float T = blk_sum(v, ws, lane, wid);
        if (tid == 0) {
            out[0] = 0.0005f * T / ((float)BN * (float)DN);
            g_sem = 0;   // reset for next replay
        }
    }
}

extern "C" void kernel_launch(void* const* d_in, const int* in_sizes, int n_in,
                              void* d_out, int out_size) {
    const float* feat  = (const float*)d_in[0];
    const int*  labels = (const int*)d_in[1];
    float* out = (float*)d_out;
    (void)in_sizes; (void)n_in; (void)out_size;

    k_hist  <<<NCHUNK, 256>>>(labels);
    k_scan  <<<1, 256>>>();
    k_rank  <<<NCHUNK, 256>>>(labels);
    k_sums  <<<CN * 4, 256>>>(feat);
    k_final2<<<CN, 256>>>(feat, out);
}

// round 13
// speedup vs baseline: 1.7469x; 1.0095x over previous
#include <cuda_runtime.h>
#include <math.h>

#define BN 32768
#define DN 1024
#define CN 256
#define MAXM 640          // max members/class (mean 128, sd ~11.3; 640 unreachable)
#define NCHUNK 128        // 32768 / 256

// Scratch — overwritten every launch where read; counters self-reset (replay safe).
__device__ __align__(16) float g_invnorm[BN];
__device__ __align__(16) int   g_order[CN * MAXM];
__device__ __align__(16) int   g_counts[CN];
__device__ __align__(16) int   g_hist[NCHUNK * CN];
__device__ __align__(16) float g_sumsP[4][CN * DN];
__device__ __align__(16) float g_partial[CN];
__device__ int g_sem1;               // k_build phase barrier
__device__ int g_sem2;               // k_build reset barrier
__device__ int g_done_cls[CN];       // per-class split completion counters
__device__ int g_sem;                // k_mega final-reduce barrier

// ---------------- K_build: hist + scan + rank fused (one launch) ---------------------
// 128 blocks, all co-resident -> internal spin barrier is safe.
__global__ void __launch_bounds__(256) k_build(const int* __restrict__ labels) {
    __shared__ int labs[256];
    __shared__ int h[CN];
    __shared__ int cb[CN];
    int tid = threadIdx.x;
    int chunk = blockIdx.x;

    // Phase 1: chunk histogram (smem int atomics -> deterministic counts)
    h[tid] = 0;
    int j = chunk * 256 + tid;
    int lab = labels[j];
    labs[tid] = lab;
    __syncthreads();
    atomicAdd(&h[lab], 1);
    __syncthreads();
    g_hist[chunk * CN + tid] = h[tid];
    __threadfence();
    if (tid == 0) {
        atomicAdd(&g_sem1, 1);
        while (*(volatile int*)&g_sem1 < NCHUNK) { }
    }
    __syncthreads();
    __threadfence();

    // Phase 2: per-class exclusive prefix for THIS chunk (thread t = class t)
    int base = 0;
    for (int b = 0; b < chunk; b++) base += g_hist[b * CN + tid];
    cb[tid] = base;
    if (chunk == NCHUNK - 1) g_counts[tid] = base + h[tid];
    __syncthreads();

    // Phase 3: within-chunk stable rank -> scatter member index
    int rank = 0;
    for (int t = 0; t < tid; t++) rank += (labs[t] == lab);
    int pos = cb[lab] + rank;
    if (pos < MAXM) g_order[lab * MAXM + pos] = j;

    // Reset counters for next replay (last block to finish)
    __threadfence();
    if (tid == 0) {
        if (atomicAdd(&g_sem2, 1) == NCHUNK - 1) { g_sem1 = 0; g_sem2 = 0; }
    }
}

// Block reduce helper: sums 'v' over 256 threads; result valid on tid 0.
__device__ __forceinline__ float blk_sum(float v, float* ws, int lane, int wid) {
    #pragma unroll
    for (int o = 16; o; o >>= 1) v += __shfl_xor_sync(0xffffffffu, v, o);
    if (lane == 0) ws[wid] = v;
    __syncthreads();
    float t = 0.f;
    if (wid == 0) {
        t = (lane < 8) ? ws[lane] : 0.f;
        #pragma unroll
        for (int o = 4; o; o >>= 1) t += __shfl_xor_sync(0xffffffffu, t, o);
    }
    __syncthreads();
    return t;  // valid on tid 0
}

// ---------------- K_mega: sums phase + per-class closed-form loss + global final -----
// grid = CN*4 (class c, split s). Sums phase identical to proven k_sums. Each split
// posts g_done_cls[c]; leader (s==0) spins for its 3 peers (adjacent bids, ~zero wait),
// then computes the class loss in closed form + rare exclusion corrections, posts a
// partial; the last leader does the deterministic final reduce and resets counters.
__global__ void __launch_bounds__(256) k_mega(const float* __restrict__ feat,
                                              float* __restrict__ out) {
    int c = blockIdx.x >> 2;
    int s = blockIdx.x & 3;
    int tid = threadIdx.x, lane = tid & 31, wid = tid >> 5;
    __shared__ float4 st4[8 * (DN / 4)];

    int n = g_counts[c];
    int n_eff = (n < MAXM) ? n : MAXM;
    const int* __restrict__ ord = g_order + c * MAXM;
    const float4* __restrict__ f4 = (const float4*)feat;

    // ================= sums phase (unchanged) =================
    float4 acc[8];
    #pragma unroll
    for (int k = 0; k < 8; k++) acc[k] = make_float4(0.f, 0.f, 0.f, 0.f);

    int gw = s * 8 + wid;           // 0..31
    int r = gw;
    for (; r + 32 < n_eff; r += 64) {
        int m0 = ord[r], m1 = ord[r + 32];
        const float4* row0 = f4 + (size_t)m0 * (DN / 4);
        const float4* row1 = f4 + (size_t)m1 * (DN / 4);
        float4 v0[8], v1[8];
        #pragma unroll
        for (int k = 0; k < 8; k++) v0[k] = row0[k * 32 + lane];
        #pragma unroll
        for (int k = 0; k < 8; k++) v1[k] = row1[k * 32 + lane];
        float s0 = 0.f, s1 = 0.f;
        #pragma unroll
        for (int k = 0; k < 8; k++) {
            s0 += v0[k].x*v0[k].x + v0[k].y*v0[k].y + v0[k].z*v0[k].z + v0[k].w*v0[k].w;
            s1 += v1[k].x*v1[k].x + v1[k].y*v1[k].y + v1[k].z*v1[k].z + v1[k].w*v1[k].w;
        }
        #pragma unroll
        for (int o = 16; o; o >>= 1) {
            s0 += __shfl_xor_sync(0xffffffffu, s0, o);
            s1 += __shfl_xor_sync(0xffffffffu, s1, o);
        }
        float i0 = rsqrtf(fmaxf(s0, 1e-24f));
        float i1 = rsqrtf(fmaxf(s1, 1e-24f));
        if (lane == 0) { g_invnorm[m0] = i0; g_invnorm[m1] = i1; }
        #pragma unroll
        for (int k = 0; k < 8; k++) {
            acc[k].x += v0[k].x*i0 + v1[k].x*i1;
            acc[k].y += v0[k].y*i0 + v1[k].y*i1;
            acc[k].z += v0[k].z*i0 + v1[k].z*i1;
            acc[k].w += v0[k].w*i0 + v1[k].w*i1;
        }
    }
    for (; r < n_eff; r += 32) {
        int m0 = ord[r];
        const float4* row0 = f4 + (size_t)m0 * (DN / 4);
        float4 v0[8];
        #pragma unroll
        for (int k = 0; k < 8; k++) v0[k] = row0[k * 32 + lane];
        float s0 = 0.f;
        #pragma unroll
        for (int k = 0; k < 8; k++)
            s0 += v0[k].x*v0[k].x + v0[k].y*v0[k].y + v0[k].z*v0[k].z + v0[k].w*v0[k].w;
        #pragma unroll
        for (int o = 16; o; o >>= 1) s0 += __shfl_xor_sync(0xffffffffu, s0, o);
        float i0 = rsqrtf(fmaxf(s0, 1e-24f));
        if (lane == 0) g_invnorm[m0] = i0;
        #pragma unroll
        for (int k = 0; k < 8; k++) {
            acc[k].x += v0[k].x*i0; acc[k].y += v0[k].y*i0;
            acc[k].z += v0[k].z*i0; acc[k].w += v0[k].w*i0;
        }
    }

    #pragma unroll
    for (int k = 0; k < 8; k++) st4[wid * (DN / 4) + k * 32 + lane] = acc[k];
    __syncthreads();
    {
        float4 t = st4[tid];
        #pragma unroll
        for (int w = 1; w < 8; w++) {
            float4 u = st4[w * (DN / 4) + tid];
            t.x += u.x; t.y += u.y; t.z += u.z; t.w += u.w;
        }
        ((float4*)g_sumsP[s])[c * (DN / 4) + tid] = t;
    }
    __threadfence();
    __syncthreads();
    if (tid == 0) atomicAdd(&g_done_cls[c], 1);
    if (s != 0) return;

    // ================= leader: wait for peers, then class loss =================
    if (tid == 0) {
        while (*(volatile int*)&g_done_cls[c] < 4) { }
    }
    __syncthreads();
    __threadfence();

    __shared__ float ws[8];
    __shared__ float bc[1];
    __shared__ int amLast;

    float4 sv;
    {
        float4 a = ((const float4*)g_sumsP[0])[c * (DN/4) + tid];
        float4 b = ((const float4*)g_sumsP[1])[c * (DN/4) + tid];
        float4 d = ((const float4*)g_sumsP[2])[c * (DN/4) + tid];
        float4 e = ((const float4*)g_sumsP[3])[c * (DN/4) + tid];
        sv.x = a.x + b.x + d.x + e.x;
        sv.y = a.y + b.y + d.y + e.y;
        sv.z = a.z + b.z + d.z + e.z;
        sv.w = a.w + b.w + d.w + e.w;
    }

    float q = sv.x*sv.x + sv.y*sv.y + sv.z*sv.z + sv.w*sv.w;
    float Q = blk_sum(q, ws, lane, wid);
    if (tid == 0) bc[0] = Q;
    __syncthreads();
    Q = bc[0];

    float raw = 0.f;                          // accumulated on tid 0 only
    if (n > 1) {
        float fn = (float)n;
        if (tid == 0) raw = fn - Q / fn;      // Σ||f_i − S/n||² with ||f_i||²=1

        // corrections: members with global index < n (ord ascending -> early break)
        float nm1 = fn - 1.0f;
        for (int rr = 0; rr < n_eff; rr++) {
            int i = ord[rr];
            if (i >= n) break;                // uniform across block
            int k2 = ord[i];                  // excluded member
            float inv_i = g_invnorm[i], inv_k = g_invnorm[k2];
            float4 va = f4[(size_t)i  * (DN/4) + tid];
            float4 vk = f4[(size_t)k2 * (DN/4) + tid];
            float pa = va.x*sv.x + va.y*sv.y + va.z*sv.z + va.w*sv.w;
            float pb = va.x*vk.x + va.y*vk.y + va.z*vk.z + va.w*vk.w;
            float pd = sv.x*vk.x + sv.y*vk.y + sv.z*vk.z + sv.w*vk.w;
            float A = blk_sum(pa, ws, lane, wid);
            float B = blk_sum(pb, ws, lane, wid);
            float D = blk_sum(pd, ws, lane, wid);
            if (tid == 0) {
                float a = A * inv_i;                 // f_i · S
                float b = B * inv_i * inv_k;         // f_i · f_k
                float d = D * inv_k;                 // S   · f_k
                float excl = -2.0f * (a - b) / nm1 + (Q - 2.0f * d + 1.0f) / (nm1 * nm1);
                float plain = -2.0f * a / fn + Q / (fn * fn);
                raw += excl - plain;
            }
        }
    }

    if (tid == 0) {
        g_partial[c] = raw;
        __threadfence();
        amLast = (atomicAdd(&g_sem, 1) == CN - 1);
    }
    __syncthreads();
    if (amLast) {
        float v = g_partial[tid];
        float T = blk_sum(v, ws, lane, wid);
        // reset counters for next replay (all leaders + splits are done by now)
        g_done_cls[tid] = 0;
        if (tid == 0) {
            out[0] = 0.0005f * T / ((float)BN * (float)DN);
            g_sem = 0;
        }
    }
}

extern "C" void kernel_launch(void* const* d_in, const int* in_sizes, int n_in,
                              void* d_out, int out_size) {
    const float* feat  = (const float*)d_in[0];
    const int*  labels = (const int*)d_in[1];
    float* out = (float*)d_out;
    (void)in_sizes; (void)n_in; (void)out_size;

    k_build<<<NCHUNK, 256>>>(labels);
    k_mega <<<CN * 4, 256>>>(feat, out);
}